// round 3
// baseline (speedup 1.0000x reference)
#include <cuda_runtime.h>
#include <math_constants.h>

// GraphSAGE fused: masked-max aggregation + relu + concat + Linear.
// B=4, N=512, C=128, OUT=128, adj ~10% dense (0.0/1.0 floats).
//
// R3 changes vs R2:
//  - GEMM phase restructured: 2-way k-split, 4 rows x 1 col per thread,
//    all 512 threads active -> 67% FFMA density (was 53%), warp-instr
//    count for the GEMM drops ~2.3x. Partials reduced via 4 KB smem.
//  - aggbuf reused as the GEMM partial buffer (smem stays ~24.5 KB so
//    2 blocks/SM stay resident -> all 256 blocks co-resident, no tail wave).

#define B_DIM 4
#define N_DIM 512
#define C_DIM 128
#define OUT_DIM 128
#define ROWS 8            // rows per block
#define THREADS 512       // 16 warps: 2 per row (aggregation)

__global__ __launch_bounds__(THREADS)
void graphsage_fused_kernel(const float* __restrict__ adj,
                            const float* __restrict__ feat,
                            const float* __restrict__ W,
                            const float* __restrict__ bias,
                            float* __restrict__ out)
{
    __shared__ __align__(16) float comb[ROWS][2 * C_DIM];            // 8 KB
    __shared__ __align__(16) float aggbuf[ROWS][2][C_DIM];           // 8 KB (reused as GEMM partials)
    __shared__ __align__(16) unsigned short idxbuf[16][264];         // 8.25 KB

    const int tid  = threadIdx.x;
    const int warp = tid >> 5;         // 0..15
    const int lane = tid & 31;
    const int row  = warp >> 1;        // 0..7 (row within block)
    const int half = warp & 1;         // which half of the adjacency row

    const int block_row0 = blockIdx.x * ROWS;
    const int grow = block_row0 + row;
    const int b = grow / N_DIM;
    const int i = grow % N_DIM;

    const float* __restrict__ fb = feat + (size_t)b * N_DIM * C_DIM;

    // ---------------- Phase 1a: own-feature copy ----------------
    if (half == 0) {
        float4 myf = reinterpret_cast<const float4*>(fb + (size_t)i * C_DIM)[lane];
        reinterpret_cast<float4*>(&comb[row][0])[lane] = myf;
    }

    // ---------------- Phase 1b: compact neighbor indices ----------------
    const float* __restrict__ adjrow =
        adj + ((size_t)b * N_DIM + i) * N_DIM + half * (N_DIM / 2);
    unsigned short* __restrict__ myidx = idxbuf[warp];
    const unsigned lt = (1u << lane) - 1u;

    int total = 0;
    #pragma unroll
    for (int c = 0; c < N_DIM / 2; c += 128) {
        float4 a = reinterpret_cast<const float4*>(adjrow + c)[lane];
        const int cbase = half * (N_DIM / 2) + c + 4 * lane;
        {
            unsigned m = __ballot_sync(0xffffffffu, a.x > 0.0f);
            if (a.x > 0.0f) myidx[total + __popc(m & lt)] = (unsigned short)(cbase + 0);
            total += __popc(m);
        }
        {
            unsigned m = __ballot_sync(0xffffffffu, a.y > 0.0f);
            if (a.y > 0.0f) myidx[total + __popc(m & lt)] = (unsigned short)(cbase + 1);
            total += __popc(m);
        }
        {
            unsigned m = __ballot_sync(0xffffffffu, a.z > 0.0f);
            if (a.z > 0.0f) myidx[total + __popc(m & lt)] = (unsigned short)(cbase + 2);
            total += __popc(m);
        }
        {
            unsigned m = __ballot_sync(0xffffffffu, a.w > 0.0f);
            if (a.w > 0.0f) myidx[total + __popc(m & lt)] = (unsigned short)(cbase + 3);
            total += __popc(m);
        }
    }
    __syncwarp();

    // ---------------- Phase 1c: gather + running max, MLP=8 ----------------
    float4 acc0 = make_float4(-CUDART_INF_F, -CUDART_INF_F, -CUDART_INF_F, -CUDART_INF_F);
    float4 acc1 = acc0, acc2 = acc0, acc3 = acc0;

    if (total > 0) {
        // pad to multiple of 8 with duplicate of last index (max is idempotent)
        const int padded = (total + 7) & ~7;
        unsigned short lastv = myidx[total - 1];
        __syncwarp();
        if (lane < padded - total) myidx[total + lane] = lastv;
        __syncwarp();

        const uint4* __restrict__ ivec = reinterpret_cast<const uint4*>(myidx);
        for (int k = 0; k < padded; k += 8) {
            uint4 I = ivec[k >> 3];
            int j0 =  I.x        & 0xffff;
            int j1 = (I.x >> 16) & 0xffff;
            int j2 =  I.y        & 0xffff;
            int j3 = (I.y >> 16) & 0xffff;
            int j4 =  I.z        & 0xffff;
            int j5 = (I.z >> 16) & 0xffff;
            int j6 =  I.w        & 0xffff;
            int j7 = (I.w >> 16) & 0xffff;

            float4 f0 = reinterpret_cast<const float4*>(fb + (size_t)j0 * C_DIM)[lane];
            float4 f1 = reinterpret_cast<const float4*>(fb + (size_t)j1 * C_DIM)[lane];
            float4 f2 = reinterpret_cast<const float4*>(fb + (size_t)j2 * C_DIM)[lane];
            float4 f3 = reinterpret_cast<const float4*>(fb + (size_t)j3 * C_DIM)[lane];
            float4 f4 = reinterpret_cast<const float4*>(fb + (size_t)j4 * C_DIM)[lane];
            float4 f5 = reinterpret_cast<const float4*>(fb + (size_t)j5 * C_DIM)[lane];
            float4 f6 = reinterpret_cast<const float4*>(fb + (size_t)j6 * C_DIM)[lane];
            float4 f7 = reinterpret_cast<const float4*>(fb + (size_t)j7 * C_DIM)[lane];

            acc0.x = fmaxf(acc0.x, f0.x); acc0.y = fmaxf(acc0.y, f0.y);
            acc0.z = fmaxf(acc0.z, f0.z); acc0.w = fmaxf(acc0.w, f0.w);
            acc1.x = fmaxf(acc1.x, f1.x); acc1.y = fmaxf(acc1.y, f1.y);
            acc1.z = fmaxf(acc1.z, f1.z); acc1.w = fmaxf(acc1.w, f1.w);
            acc2.x = fmaxf(acc2.x, f2.x); acc2.y = fmaxf(acc2.y, f2.y);
            acc2.z = fmaxf(acc2.z, f2.z); acc2.w = fmaxf(acc2.w, f2.w);
            acc3.x = fmaxf(acc3.x, f3.x); acc3.y = fmaxf(acc3.y, f3.y);
            acc3.z = fmaxf(acc3.z, f3.z); acc3.w = fmaxf(acc3.w, f3.w);

            acc0.x = fmaxf(acc0.x, f4.x); acc0.y = fmaxf(acc0.y, f4.y);
            acc0.z = fmaxf(acc0.z, f4.z); acc0.w = fmaxf(acc0.w, f4.w);
            acc1.x = fmaxf(acc1.x, f5.x); acc1.y = fmaxf(acc1.y, f5.y);
            acc1.z = fmaxf(acc1.z, f5.z); acc1.w = fmaxf(acc1.w, f5.w);
            acc2.x = fmaxf(acc2.x, f6.x); acc2.y = fmaxf(acc2.y, f6.y);
            acc2.z = fmaxf(acc2.z, f6.z); acc2.w = fmaxf(acc2.w, f6.w);
            acc3.x = fmaxf(acc3.x, f7.x); acc3.y = fmaxf(acc3.y, f7.y);
            acc3.z = fmaxf(acc3.z, f7.z); acc3.w = fmaxf(acc3.w, f7.w);
        }
    }

    float4 accA;
    accA.x = fmaxf(fmaxf(acc0.x, acc1.x), fmaxf(acc2.x, acc3.x));
    accA.y = fmaxf(fmaxf(acc0.y, acc1.y), fmaxf(acc2.y, acc3.y));
    accA.z = fmaxf(fmaxf(acc0.z, acc1.z), fmaxf(acc2.z, acc3.z));
    accA.w = fmaxf(fmaxf(acc0.w, acc1.w), fmaxf(acc2.w, acc3.w));
    reinterpret_cast<float4*>(&aggbuf[row][half][0])[lane] = accA;

    __syncthreads();

    // ---------------- Phase 1d: combine halves + relu ----------------
    #pragma unroll
    for (int t = tid; t < ROWS * C_DIM; t += THREADS) {
        int r = t >> 7;
        int c = t & (C_DIM - 1);
        comb[r][C_DIM + c] = fmaxf(0.0f, fmaxf(aggbuf[r][0][c], aggbuf[r][1][c]));
    }
    __syncthreads();

    // ---------------- Phase 2: fused linear layer ----------------
    // 2-way k-split: thread t -> col o = t&127, g = t>>7:
    //   row quad  rq = (g & 1) * 4   (rows rq..rq+3)
    //   k half    kh = g >> 1        (input channels kh*128 .. kh*128+127)
    // Each thread: 4 rows x 1 col partial over 128 channels.
    // kh==1 partials go through smem (reusing aggbuf), kh==0 adds + stores.
    {
        const int o  = tid & (OUT_DIM - 1);
        const int g  = tid >> 7;
        const int rq = (g & 1) * 4;
        const int kh = g >> 1;

        float a0 = 0.f, a1 = 0.f, a2 = 0.f, a3 = 0.f;

        const float4* __restrict__ c0 =
            reinterpret_cast<const float4*>(&comb[rq + 0][kh * C_DIM]);
        const float4* __restrict__ c1 =
            reinterpret_cast<const float4*>(&comb[rq + 1][kh * C_DIM]);
        const float4* __restrict__ c2 =
            reinterpret_cast<const float4*>(&comb[rq + 2][kh * C_DIM]);
        const float4* __restrict__ c3 =
            reinterpret_cast<const float4*>(&comb[rq + 3][kh * C_DIM]);
        const float* __restrict__ wbase = W + (size_t)(kh * C_DIM) * OUT_DIM + o;

        #pragma unroll 8
        for (int c4 = 0; c4 < C_DIM / 4; ++c4) {
            float4 f0 = c0[c4];
            float4 f1 = c1[c4];
            float4 f2 = c2[c4];
            float4 f3 = c3[c4];
            const float* __restrict__ wp = wbase + (size_t)c4 * 4 * OUT_DIM;
            float w0 = wp[0 * OUT_DIM];
            float w1 = wp[1 * OUT_DIM];
            float w2 = wp[2 * OUT_DIM];
            float w3 = wp[3 * OUT_DIM];

            a0 += f0.x * w0; a0 += f0.y * w1; a0 += f0.z * w2; a0 += f0.w * w3;
            a1 += f1.x * w0; a1 += f1.y * w1; a1 += f1.z * w2; a1 += f1.w * w3;
            a2 += f2.x * w0; a2 += f2.y * w1; a2 += f2.z * w2; a2 += f2.w * w3;
            a3 += f3.x * w0; a3 += f3.y * w1; a3 += f3.z * w2; a3 += f3.w * w3;
        }

        // reduce the two k-halves via smem (reuse aggbuf: 8*128 floats)
        float* __restrict__ ps = &aggbuf[0][0][0];   // [8][128]
        if (kh == 1) {
            ps[(rq + 0) * OUT_DIM + o] = a0;
            ps[(rq + 1) * OUT_DIM + o] = a1;
            ps[(rq + 2) * OUT_DIM + o] = a2;
            ps[(rq + 3) * OUT_DIM + o] = a3;
        }
        __syncthreads();
        if (kh == 0) {
            const float bv = bias[o];
            const size_t orow = (size_t)(block_row0 + rq);
            out[(orow + 0) * OUT_DIM + o] = a0 + ps[(rq + 0) * OUT_DIM + o] + bv;
            out[(orow + 1) * OUT_DIM + o] = a1 + ps[(rq + 1) * OUT_DIM + o] + bv;
            out[(orow + 2) * OUT_DIM + o] = a2 + ps[(rq + 2) * OUT_DIM + o] + bv;
            out[(orow + 3) * OUT_DIM + o] = a3 + ps[(rq + 3) * OUT_DIM + o] + bv;
        }
    }
}

extern "C" void kernel_launch(void* const* d_in, const int* in_sizes, int n_in,
                              void* d_out, int out_size)
{
    (void)in_sizes; (void)n_in; (void)out_size;
    const float* adj  = (const float*)d_in[0];   // [B,N,N]
    const float* feat = (const float*)d_in[1];   // [B,N,C]
    const float* W    = (const float*)d_in[2];   // [2C,OUT]
    const float* bias = (const float*)d_in[3];   // [OUT]
    float* out        = (float*)d_out;           // [B,N,OUT]

    dim3 grid((B_DIM * N_DIM) / ROWS);
    dim3 block(THREADS);
    graphsage_fused_kernel<<<grid, block>>>(adj, feat, W, bias, out);
}

// round 4
// speedup vs baseline: 1.4320x; 1.4320x over previous
#include <cuda_runtime.h>
#include <math_constants.h>

// GraphSAGE fused: masked-max aggregation + relu + concat + Linear.
// B=4, N=512, C=128, OUT=128, adj ~10% dense (0.0/1.0 floats).
//
// R4 (vs R2 which ran 17.2us):
//  - aggregation phase IDENTICAL to R2 (2 warps/row, ballot-compact, MLP=8)
//  - combined matrix stored k-major interleaved: combT[k][8 rows]
//  - GEMM: k-split x4 so each W element is loaded exactly ONCE per block
//    (W L1 wavefronts per block 4096 -> 1024), packed fma.rn.f32x2 (FFMA2)
//    halves FMA instruction count; split-k reduced via smem.

#define B_DIM 4
#define N_DIM 512
#define C_DIM 128
#define OUT_DIM 128
#define ROWS 8            // rows per block
#define THREADS 512       // 16 warps: 2 per row (aggregation)

__global__ __launch_bounds__(THREADS)
void graphsage_fused_kernel(const float* __restrict__ adj,
                            const float* __restrict__ feat,
                            const float* __restrict__ W,
                            const float* __restrict__ bias,
                            float* __restrict__ out)
{
    // combT[k][r]: k-major interleaved combined matrix (features ++ neigh)
    __shared__ __align__(16) float combT[2 * C_DIM][ROWS];          // 8 KB
    // scratch: aggregation buffers, later reused as split-k partials (12 KB)
    __shared__ __align__(16) char scratch[8192 + 16 * 264 * 2];     // 16.4 KB

    float (*aggbuf)[2][C_DIM] = reinterpret_cast<float (*)[2][C_DIM]>(scratch);
    unsigned short (*idxbuf)[264] =
        reinterpret_cast<unsigned short (*)[264]>(scratch + 8192);
    float* ps = reinterpret_cast<float*>(scratch);   // [3][ROWS][OUT] partials

    const int tid  = threadIdx.x;
    const int warp = tid >> 5;         // 0..15
    const int lane = tid & 31;
    const int row  = warp >> 1;        // 0..7 (row within block)
    const int half = warp & 1;         // which half of the adjacency row

    const int block_row0 = blockIdx.x * ROWS;
    const int grow = block_row0 + row;
    const int b = grow / N_DIM;
    const int i = grow % N_DIM;

    const float* __restrict__ fb = feat + (size_t)b * N_DIM * C_DIM;

    // ---------------- Phase 1a: compact neighbor indices ----------------
    const float* __restrict__ adjrow =
        adj + ((size_t)b * N_DIM + i) * N_DIM + half * (N_DIM / 2);
    unsigned short* __restrict__ myidx = idxbuf[warp];
    const unsigned lt = (1u << lane) - 1u;

    int total = 0;
    #pragma unroll
    for (int c = 0; c < N_DIM / 2; c += 128) {
        float4 a = reinterpret_cast<const float4*>(adjrow + c)[lane];
        const int cbase = half * (N_DIM / 2) + c + 4 * lane;
        {
            unsigned m = __ballot_sync(0xffffffffu, a.x > 0.0f);
            if (a.x > 0.0f) myidx[total + __popc(m & lt)] = (unsigned short)(cbase + 0);
            total += __popc(m);
        }
        {
            unsigned m = __ballot_sync(0xffffffffu, a.y > 0.0f);
            if (a.y > 0.0f) myidx[total + __popc(m & lt)] = (unsigned short)(cbase + 1);
            total += __popc(m);
        }
        {
            unsigned m = __ballot_sync(0xffffffffu, a.z > 0.0f);
            if (a.z > 0.0f) myidx[total + __popc(m & lt)] = (unsigned short)(cbase + 2);
            total += __popc(m);
        }
        {
            unsigned m = __ballot_sync(0xffffffffu, a.w > 0.0f);
            if (a.w > 0.0f) myidx[total + __popc(m & lt)] = (unsigned short)(cbase + 3);
            total += __popc(m);
        }
    }
    __syncwarp();

    // ---------------- Phase 1b: gather + running max, MLP=8 ----------------
    float4 acc0 = make_float4(-CUDART_INF_F, -CUDART_INF_F, -CUDART_INF_F, -CUDART_INF_F);
    float4 acc1 = acc0, acc2 = acc0, acc3 = acc0;

    if (total > 0) {
        const int padded = (total + 7) & ~7;
        unsigned short lastv = myidx[total - 1];
        __syncwarp();
        if (lane < padded - total) myidx[total + lane] = lastv;
        __syncwarp();

        const uint4* __restrict__ ivec = reinterpret_cast<const uint4*>(myidx);
        for (int k = 0; k < padded; k += 8) {
            uint4 I = ivec[k >> 3];
            int j0 =  I.x        & 0xffff;
            int j1 = (I.x >> 16) & 0xffff;
            int j2 =  I.y        & 0xffff;
            int j3 = (I.y >> 16) & 0xffff;
            int j4 =  I.z        & 0xffff;
            int j5 = (I.z >> 16) & 0xffff;
            int j6 =  I.w        & 0xffff;
            int j7 = (I.w >> 16) & 0xffff;

            float4 f0 = reinterpret_cast<const float4*>(fb + (size_t)j0 * C_DIM)[lane];
            float4 f1 = reinterpret_cast<const float4*>(fb + (size_t)j1 * C_DIM)[lane];
            float4 f2 = reinterpret_cast<const float4*>(fb + (size_t)j2 * C_DIM)[lane];
            float4 f3 = reinterpret_cast<const float4*>(fb + (size_t)j3 * C_DIM)[lane];
            float4 f4 = reinterpret_cast<const float4*>(fb + (size_t)j4 * C_DIM)[lane];
            float4 f5 = reinterpret_cast<const float4*>(fb + (size_t)j5 * C_DIM)[lane];
            float4 f6 = reinterpret_cast<const float4*>(fb + (size_t)j6 * C_DIM)[lane];
            float4 f7 = reinterpret_cast<const float4*>(fb + (size_t)j7 * C_DIM)[lane];

            acc0.x = fmaxf(acc0.x, f0.x); acc0.y = fmaxf(acc0.y, f0.y);
            acc0.z = fmaxf(acc0.z, f0.z); acc0.w = fmaxf(acc0.w, f0.w);
            acc1.x = fmaxf(acc1.x, f1.x); acc1.y = fmaxf(acc1.y, f1.y);
            acc1.z = fmaxf(acc1.z, f1.z); acc1.w = fmaxf(acc1.w, f1.w);
            acc2.x = fmaxf(acc2.x, f2.x); acc2.y = fmaxf(acc2.y, f2.y);
            acc2.z = fmaxf(acc2.z, f2.z); acc2.w = fmaxf(acc2.w, f2.w);
            acc3.x = fmaxf(acc3.x, f3.x); acc3.y = fmaxf(acc3.y, f3.y);
            acc3.z = fmaxf(acc3.z, f3.z); acc3.w = fmaxf(acc3.w, f3.w);

            acc0.x = fmaxf(acc0.x, f4.x); acc0.y = fmaxf(acc0.y, f4.y);
            acc0.z = fmaxf(acc0.z, f4.z); acc0.w = fmaxf(acc0.w, f4.w);
            acc1.x = fmaxf(acc1.x, f5.x); acc1.y = fmaxf(acc1.y, f5.y);
            acc1.z = fmaxf(acc1.z, f5.z); acc1.w = fmaxf(acc1.w, f5.w);
            acc2.x = fmaxf(acc2.x, f6.x); acc2.y = fmaxf(acc2.y, f6.y);
            acc2.z = fmaxf(acc2.z, f6.z); acc2.w = fmaxf(acc2.w, f6.w);
            acc3.x = fmaxf(acc3.x, f7.x); acc3.y = fmaxf(acc3.y, f7.y);
            acc3.z = fmaxf(acc3.z, f7.z); acc3.w = fmaxf(acc3.w, f7.w);
        }
    }

    float4 accA;
    accA.x = fmaxf(fmaxf(acc0.x, acc1.x), fmaxf(acc2.x, acc3.x));
    accA.y = fmaxf(fmaxf(acc0.y, acc1.y), fmaxf(acc2.y, acc3.y));
    accA.z = fmaxf(fmaxf(acc0.z, acc1.z), fmaxf(acc2.z, acc3.z));
    accA.w = fmaxf(fmaxf(acc0.w, acc1.w), fmaxf(acc2.w, acc3.w));
    reinterpret_cast<float4*>(&aggbuf[row][half][0])[lane] = accA;

    __syncthreads();

    // ---- Phase 1c: build combT (feature copy + combine halves + relu) ----
    // mapping: r = tid&7, c8 = tid>>3 -> conflict-free STS into combT
    {
        const int r  = tid & 7;
        const int c8 = tid >> 3;          // 0..63
        const int gr = block_row0 + r;
        const int rb = gr / N_DIM;
        const int ri = gr % N_DIM;
        const float* __restrict__ frow =
            feat + ((size_t)rb * N_DIM + ri) * C_DIM;
        #pragma unroll
        for (int j = 0; j < 2; ++j) {
            const int c = c8 + 64 * j;
            combT[c][r] = frow[c];
            combT[C_DIM + c][r] =
                fmaxf(0.0f, fmaxf(aggbuf[r][0][c], aggbuf[r][1][c]));
        }
    }
    __syncthreads();

    // ---------------- Phase 2: fused linear layer ----------------
    // thread t: o = t&127, ks = t>>7 (4-way k-split, 64 k each).
    // Each thread: 8 rows x 1 col over its 64 k-slice. W read once per block.
    // Packed f32x2 FMA: combT[k][0..7] = two 16B LDS, W packed {w,w}.
    {
        const int o  = tid & (OUT_DIM - 1);
        const int ks = tid >> 7;

        const float* __restrict__ wp = W + (size_t)(ks * 64) * OUT_DIM + o;
        const float* __restrict__ cb = &combT[ks * 64][0];

        unsigned long long a01 = 0ull, a23 = 0ull, a45 = 0ull, a67 = 0ull;

        #pragma unroll 8
        for (int k = 0; k < 64; ++k) {
            float w = wp[(size_t)k * OUT_DIM];
            unsigned long long wpk;
            asm("mov.b64 %0, {%1, %1};" : "=l"(wpk) : "f"(w));

            const double2 q0 = *reinterpret_cast<const double2*>(cb + k * 8);
            const double2 q1 = *reinterpret_cast<const double2*>(cb + k * 8 + 4);
            unsigned long long p01 = __double_as_longlong(q0.x);
            unsigned long long p23 = __double_as_longlong(q0.y);
            unsigned long long p45 = __double_as_longlong(q1.x);
            unsigned long long p67 = __double_as_longlong(q1.y);

            asm("fma.rn.f32x2 %0, %1, %2, %0;" : "+l"(a01) : "l"(p01), "l"(wpk));
            asm("fma.rn.f32x2 %0, %1, %2, %0;" : "+l"(a23) : "l"(p23), "l"(wpk));
            asm("fma.rn.f32x2 %0, %1, %2, %0;" : "+l"(a45) : "l"(p45), "l"(wpk));
            asm("fma.rn.f32x2 %0, %1, %2, %0;" : "+l"(a67) : "l"(p67), "l"(wpk));
        }

        float r0, r1, r2, r3, r4, r5, r6, r7;
        asm("mov.b64 {%0, %1}, %2;" : "=f"(r0), "=f"(r1) : "l"(a01));
        asm("mov.b64 {%0, %1}, %2;" : "=f"(r2), "=f"(r3) : "l"(a23));
        asm("mov.b64 {%0, %1}, %2;" : "=f"(r4), "=f"(r5) : "l"(a45));
        asm("mov.b64 {%0, %1}, %2;" : "=f"(r6), "=f"(r7) : "l"(a67));

        if (ks != 0) {
            float* p = ps + (size_t)(ks - 1) * ROWS * OUT_DIM + o;
            p[0 * OUT_DIM] = r0;  p[1 * OUT_DIM] = r1;
            p[2 * OUT_DIM] = r2;  p[3 * OUT_DIM] = r3;
            p[4 * OUT_DIM] = r4;  p[5 * OUT_DIM] = r5;
            p[6 * OUT_DIM] = r6;  p[7 * OUT_DIM] = r7;
        }
        __syncthreads();
        if (ks == 0) {
            const float bv = bias[o];
            const float* p0 = ps + o;
            const float* p1 = ps + ROWS * OUT_DIM + o;
            const float* p2 = ps + 2 * ROWS * OUT_DIM + o;
            float* __restrict__ op = out + (size_t)block_row0 * OUT_DIM + o;
            op[0 * OUT_DIM] = r0 + p0[0 * OUT_DIM] + p1[0 * OUT_DIM] + p2[0 * OUT_DIM] + bv;
            op[1 * OUT_DIM] = r1 + p0[1 * OUT_DIM] + p1[1 * OUT_DIM] + p2[1 * OUT_DIM] + bv;
            op[2 * OUT_DIM] = r2 + p0[2 * OUT_DIM] + p1[2 * OUT_DIM] + p2[2 * OUT_DIM] + bv;
            op[3 * OUT_DIM] = r3 + p0[3 * OUT_DIM] + p1[3 * OUT_DIM] + p2[3 * OUT_DIM] + bv;
            op[4 * OUT_DIM] = r4 + p0[4 * OUT_DIM] + p1[4 * OUT_DIM] + p2[4 * OUT_DIM] + bv;
            op[5 * OUT_DIM] = r5 + p0[5 * OUT_DIM] + p1[5 * OUT_DIM] + p2[5 * OUT_DIM] + bv;
            op[6 * OUT_DIM] = r6 + p0[6 * OUT_DIM] + p1[6 * OUT_DIM] + p2[6 * OUT_DIM] + bv;
            op[7 * OUT_DIM] = r7 + p0[7 * OUT_DIM] + p1[7 * OUT_DIM] + p2[7 * OUT_DIM] + bv;
        }
    }
}

extern "C" void kernel_launch(void* const* d_in, const int* in_sizes, int n_in,
                              void* d_out, int out_size)
{
    (void)in_sizes; (void)n_in; (void)out_size;
    const float* adj  = (const float*)d_in[0];   // [B,N,N]
    const float* feat = (const float*)d_in[1];   // [B,N,C]
    const float* W    = (const float*)d_in[2];   // [2C,OUT]
    const float* bias = (const float*)d_in[3];   // [OUT]
    float* out        = (float*)d_out;           // [B,N,OUT]

    dim3 grid((B_DIM * N_DIM) / ROWS);
    dim3 block(THREADS);
    graphsage_fused_kernel<<<grid, block>>>(adj, feat, W, bias, out);
}